// round 7
// baseline (speedup 1.0000x reference)
#include <cuda_runtime.h>

// PAU rational activation: out = P(z)/Q(z), z = x + center.
// x: [16,2048,4096] f32 (N = 134217728), center[1], numerator[6], denominator[4].
// Fabric-bound at ~6.75 TB/s (measured ceiling across 4 launch shapes).
// This round: 512-thread blocks, 4 front-batched float4/thread (8192-elem
// CTA tile) -> longer contiguous per-CTA streams for DRAM row locality.

struct PauParams {
    float c;
    float a0, a1, a2, a3, a4, a5;
    float b0, b1, b2, b3;   // already |.|'d at load time
};

__device__ __forceinline__ float pau_one(float x, const PauParams& P) {
    float z = x + P.c;
    float p = P.a5;
    p = fmaf(p, z, P.a4);
    p = fmaf(p, z, P.a3);
    p = fmaf(p, z, P.a2);
    p = fmaf(p, z, P.a1);
    p = fmaf(p, z, P.a0);
    float az = fabsf(z);
    float q = P.b3;
    q = fmaf(q, az, P.b2);
    q = fmaf(q, az, P.b1);
    q = fmaf(q, az, P.b0);
    q = fmaf(q, az, 1.0f);
    // fast division: MUFU.RCP + FMUL, err ~2^-21 << 1e-3 tolerance
    return __fdividef(p, q);
}

__device__ __forceinline__ float4 pau_vec(float4 v, const PauParams& P) {
    float4 r;
    r.x = pau_one(v.x, P);
    r.y = pau_one(v.y, P);
    r.z = pau_one(v.z, P);
    r.w = pau_one(v.w, P);
    return r;
}

__device__ __forceinline__ PauParams load_params(
    const float* __restrict__ center,
    const float* __restrict__ num,
    const float* __restrict__ den) {
    PauParams P;
    P.c  = __ldg(center);
    P.a0 = __ldg(num + 0); P.a1 = __ldg(num + 1); P.a2 = __ldg(num + 2);
    P.a3 = __ldg(num + 3); P.a4 = __ldg(num + 4); P.a5 = __ldg(num + 5);
    P.b0 = fabsf(__ldg(den + 0)); P.b1 = fabsf(__ldg(den + 1));
    P.b2 = fabsf(__ldg(den + 2)); P.b3 = fabsf(__ldg(den + 3));
    return P;
}

// 512 threads/block, each thread processes 4 float4 (16 elems).
// Block covers 2048 contiguous float4s = 32 KB in / 32 KB out.
__global__ void __launch_bounds__(512) pau_kernel512(
    const float4* __restrict__ x4, float4* __restrict__ o4,
    const float* __restrict__ center,
    const float* __restrict__ num,
    const float* __restrict__ den) {
    const PauParams P = load_params(center, num, den);

    unsigned base = blockIdx.x * 2048u + threadIdx.x;
    float4 v0 = __ldcs(x4 + base);
    float4 v1 = __ldcs(x4 + base + 512u);
    float4 v2 = __ldcs(x4 + base + 1024u);
    float4 v3 = __ldcs(x4 + base + 1536u);
    __stcs(o4 + base,         pau_vec(v0, P));
    __stcs(o4 + base + 512u,  pau_vec(v1, P));
    __stcs(o4 + base + 1024u, pau_vec(v2, P));
    __stcs(o4 + base + 1536u, pau_vec(v3, P));
}

// Generic tail kernel for leftover elements (not launched for this shape:
// N = 2^27 is an exact multiple of the 8192-element block tile).
__global__ void pau_tail(const float* __restrict__ x, float* __restrict__ out,
                         const float* __restrict__ center,
                         const float* __restrict__ num,
                         const float* __restrict__ den,
                         long long start, long long n) {
    const PauParams P = load_params(center, num, den);
    long long i = start + (long long)blockIdx.x * blockDim.x + threadIdx.x;
    if (i < n) out[i] = pau_one(x[i], P);
}

extern "C" void kernel_launch(void* const* d_in, const int* in_sizes, int n_in,
                              void* d_out, int out_size) {
    const float* x = (const float*)d_in[0];
    const float* center = (const float*)d_in[1];
    const float* numerator = (const float*)d_in[2];
    const float* denominator = (const float*)d_in[3];
    float* out = (float*)d_out;

    long long n = (long long)in_sizes[0];
    long long n4 = n / 4;
    long long nblocks = n4 / 2048;       // each block covers 8192 elements
    long long covered = nblocks * 8192;

    if (nblocks > 0) {
        pau_kernel512<<<(unsigned)nblocks, 512>>>(
            (const float4*)x, (float4*)out, center, numerator, denominator);
    }
    if (covered < n) {
        long long rem = n - covered;
        int tb = (int)((rem + 255) / 256);
        pau_tail<<<tb, 256>>>(x, out, center, numerator, denominator, covered, n);
    }
}

// round 8
// speedup vs baseline: 1.0022x; 1.0022x over previous
#include <cuda_runtime.h>

// PAU rational activation: out = P(z)/Q(z), z = x + center.
// x: [16,2048,4096] f32 (N = 134217728), center[1], numerator[6], denominator[4].
//
// FINAL kernel. Fabric-bound: 1 GiB irreducible traffic at the measured
// chip streaming ceiling (~6.75 TB/s; 5 launch shapes all within ±0.7%).
// Optimal measured shape: flat grid, 256 thr/block, 4 front-batched
// float4/thread (MLP_p1=4), params via __ldg broadcast (single graph node),
// fast-divide epilogue (err ~2^-21 << 1e-3 gate).

struct PauParams {
    float c;
    float a0, a1, a2, a3, a4, a5;
    float b0, b1, b2, b3;   // already |.|'d at load time
};

__device__ __forceinline__ float pau_one(float x, const PauParams& P) {
    float z = x + P.c;
    float p = P.a5;
    p = fmaf(p, z, P.a4);
    p = fmaf(p, z, P.a3);
    p = fmaf(p, z, P.a2);
    p = fmaf(p, z, P.a1);
    p = fmaf(p, z, P.a0);
    float az = fabsf(z);
    float q = P.b3;
    q = fmaf(q, az, P.b2);
    q = fmaf(q, az, P.b1);
    q = fmaf(q, az, P.b0);
    q = fmaf(q, az, 1.0f);
    // fast division: MUFU.RCP + FMUL, err ~2^-21 << 1e-3 tolerance
    return __fdividef(p, q);
}

__device__ __forceinline__ float4 pau_vec(float4 v, const PauParams& P) {
    float4 r;
    r.x = pau_one(v.x, P);
    r.y = pau_one(v.y, P);
    r.z = pau_one(v.z, P);
    r.w = pau_one(v.w, P);
    return r;
}

__device__ __forceinline__ PauParams load_params(
    const float* __restrict__ center,
    const float* __restrict__ num,
    const float* __restrict__ den) {
    PauParams P;
    P.c  = __ldg(center);
    P.a0 = __ldg(num + 0); P.a1 = __ldg(num + 1); P.a2 = __ldg(num + 2);
    P.a3 = __ldg(num + 3); P.a4 = __ldg(num + 4); P.a5 = __ldg(num + 5);
    P.b0 = fabsf(__ldg(den + 0)); P.b1 = fabsf(__ldg(den + 1));
    P.b2 = fabsf(__ldg(den + 2)); P.b3 = fabsf(__ldg(den + 3));
    return P;
}

// Main kernel: 256 threads/block, each thread processes 4 float4 (16 elems).
// All 4 loads front-batched and independent; block covers 1024 contiguous
// float4s so every 128B line is fully coalesced.
__global__ void __launch_bounds__(256) pau_kernel16(
    const float4* __restrict__ x4, float4* __restrict__ o4,
    const float* __restrict__ center,
    const float* __restrict__ num,
    const float* __restrict__ den) {
    const PauParams P = load_params(center, num, den);

    unsigned base = blockIdx.x * 1024u + threadIdx.x;
    float4 v0 = __ldcs(x4 + base);
    float4 v1 = __ldcs(x4 + base + 256u);
    float4 v2 = __ldcs(x4 + base + 512u);
    float4 v3 = __ldcs(x4 + base + 768u);
    __stcs(o4 + base,        pau_vec(v0, P));
    __stcs(o4 + base + 256u, pau_vec(v1, P));
    __stcs(o4 + base + 512u, pau_vec(v2, P));
    __stcs(o4 + base + 768u, pau_vec(v3, P));
}

// Generic tail kernel for leftover elements (not launched for this shape:
// N = 2^27 is an exact multiple of the 4096-element block tile).
__global__ void pau_tail(const float* __restrict__ x, float* __restrict__ out,
                         const float* __restrict__ center,
                         const float* __restrict__ num,
                         const float* __restrict__ den,
                         long long start, long long n) {
    const PauParams P = load_params(center, num, den);
    long long i = start + (long long)blockIdx.x * blockDim.x + threadIdx.x;
    if (i < n) out[i] = pau_one(x[i], P);
}

extern "C" void kernel_launch(void* const* d_in, const int* in_sizes, int n_in,
                              void* d_out, int out_size) {
    const float* x = (const float*)d_in[0];
    const float* center = (const float*)d_in[1];
    const float* numerator = (const float*)d_in[2];
    const float* denominator = (const float*)d_in[3];
    float* out = (float*)d_out;

    long long n = (long long)in_sizes[0];
    long long n4 = n / 4;
    long long nblocks = n4 / 1024;       // each block covers 4096 elements
    long long covered = nblocks * 4096;

    if (nblocks > 0) {
        pau_kernel16<<<(unsigned)nblocks, 256>>>(
            (const float4*)x, (float4*)out, center, numerator, denominator);
    }
    if (covered < n) {
        long long rem = n - covered;
        int tb = (int)((rem + 255) / 256);
        pau_tail<<<tb, 256>>>(x, out, center, numerator, denominator, covered, n);
    }
}